// round 1
// baseline (speedup 1.0000x reference)
#include <cuda_runtime.h>

#define T_ 1132
#define B_ 128
#define H_ 13
#define L_ 100
#define TH_ 14716
#define C_ 10

// Scratch: double-buffered layer activations + per-timestep progress flags.
// (static __device__ arrays: allowed; no allocation anywhere)
__device__ float g_buf[2][T_][B_][16];   // [parity][t][b][padded H] ~18.5MB
__device__ int   g_prog[T_];             // number of layers that finished t

__device__ __forceinline__ int ld_acq(const int* p) {
    int v;
    asm volatile("ld.acquire.gpu.global.b32 %0, [%1];" : "=r"(v) : "l"(p) : "memory");
    return v;
}
__device__ __forceinline__ void st_rel(int* p, int v) {
    asm volatile("st.release.gpu.global.b32 [%0], %1;" :: "l"(p), "r"(v) : "memory");
}

__device__ __forceinline__ float sigf(float x) {
    // 1/(1+e^-x) via MUFU EX2 + approx divide (rel err ~1e-6)
    return __fdividef(1.0f, 1.0f + __expf(-x));
}
__device__ __forceinline__ float tanh_f(float x) {
    // sign-symmetric: e = exp(-2|x|) in (0,1], no inf/inf
    float a = fabsf(x);
    float e = __expf(-2.0f * a);
    float t = __fdividef(1.0f - e, 1.0f + e);
    return copysignf(t, x);
}

__global__ void k_reset() {
    int i = blockIdx.x * blockDim.x + threadIdx.x;
    if (i < T_) g_prog[i] = 0;
}

// One CTA per layer, one thread per batch element. Wavefront pipeline over t.
__global__ __launch_bounds__(128, 1) void k_lstm(
    const float* __restrict__ input,
    const float* __restrict__ w_ih, const float* __restrict__ w_hh,
    const float* __restrict__ b_ih, const float* __restrict__ b_hh)
{
    // weights rearranged per hidden-unit j, gate g, padded to 14 (7 float2)
    __shared__ float2 s_wi[13][4][7];
    __shared__ float2 s_wh[13][4][7];
    __shared__ float  s_b[13][4];
    __shared__ float  s_c[B_ * 13];   // per-thread cell state (private slots)
    __shared__ float  s_hn[B_ * 13];  // new h staging (avoids reg-indexed arrays)

    const int l = blockIdx.x;
    const int b = threadIdx.x;

    // --- load + transform weights ---
    {
        float* pi = (float*)s_wi;
        float* ph = (float*)s_wh;
        for (int i = b; i < 13 * 4 * 14; i += 128) { pi[i] = 0.0f; ph[i] = 0.0f; }
    }
    __syncthreads();
    {
        float* pi = (float*)s_wi;
        float* ph = (float*)s_wh;
        for (int i = b; i < 52 * 13; i += 128) {
            int r = i / 13, k = i % 13;      // r = gate-row (g*13+j), k = input col
            int g = r / 13, j = r % 13;
            pi[(j * 4 + g) * 14 + k] = w_ih[(l * 52 + r) * 13 + k];
            ph[(j * 4 + g) * 14 + k] = w_hh[(l * 52 + r) * 13 + k];
        }
        for (int i = b; i < 52; i += 128) {
            int g = i / 13, j = i % 13;
            s_b[j][g] = b_ih[l * 52 + i] + b_hh[l * 52 + i];
        }
    }

    // --- init state ---
    float h[14], x[14];
    #pragma unroll
    for (int k = 0; k < 14; k++) { h[k] = 0.0f; x[k] = 0.0f; }
    #pragma unroll
    for (int j = 0; j < 13; j++) s_c[b * 13 + j] = 0.0f;
    __syncthreads();

    const int wp = l & 1;    // write parity
    const int rp = wp ^ 1;   // read parity

    for (int t = 0; t < T_; t++) {
        // ---- obtain x(t) ----
        if (l == 0) {
            #pragma unroll
            for (int k = 0; k < 13; k++) x[k] = input[(b * T_ + t) * 13 + k];
        } else {
            if (b == 0) {
                while (ld_acq(&g_prog[t]) < l) __nanosleep(32);
            }
            __syncthreads();  // all threads see producer's data via t0's acquire
            const float4* src = (const float4*)&g_buf[rp][t][b][0];
            float4 v0 = src[0], v1 = src[1], v2 = src[2];
            float  vx = g_buf[rp][t][b][12];
            x[0] = v0.x; x[1] = v0.y; x[2]  = v0.z; x[3]  = v0.w;
            x[4] = v1.x; x[5] = v1.y; x[6]  = v1.z; x[7]  = v1.w;
            x[8] = v2.x; x[9] = v2.y; x[10] = v2.z; x[11] = v2.w;
            x[12] = vx;   // x[13] stays 0 (pad)
        }

        // ---- gates + state update, per hidden unit j ----
        #pragma unroll 1
        for (int j = 0; j < 13; j++) {
            float cj = s_c[b * 13 + j];
            float ai = s_b[j][0], af = s_b[j][1], ag = s_b[j][2], ao = s_b[j][3];
            #pragma unroll
            for (int kk = 0; kk < 7; kk++) {
                float2 wi0 = s_wi[j][0][kk], wh0 = s_wh[j][0][kk];
                float2 wi1 = s_wi[j][1][kk], wh1 = s_wh[j][1][kk];
                float2 wi2 = s_wi[j][2][kk], wh2 = s_wh[j][2][kk];
                float2 wi3 = s_wi[j][3][kk], wh3 = s_wh[j][3][kk];
                float x0 = x[2 * kk], x1 = x[2 * kk + 1];
                float h0 = h[2 * kk], h1 = h[2 * kk + 1];
                ai = fmaf(wi0.x, x0, ai); ai = fmaf(wi0.y, x1, ai);
                af = fmaf(wi1.x, x0, af); af = fmaf(wi1.y, x1, af);
                ag = fmaf(wi2.x, x0, ag); ag = fmaf(wi2.y, x1, ag);
                ao = fmaf(wi3.x, x0, ao); ao = fmaf(wi3.y, x1, ao);
                ai = fmaf(wh0.x, h0, ai); ai = fmaf(wh0.y, h1, ai);
                af = fmaf(wh1.x, h0, af); af = fmaf(wh1.y, h1, af);
                ag = fmaf(wh2.x, h0, ag); ag = fmaf(wh2.y, h1, ag);
                ao = fmaf(wh3.x, h0, ao); ao = fmaf(wh3.y, h1, ao);
            }
            float ig = sigf(ai), fg = sigf(af), gv = tanh_f(ag), og = sigf(ao);
            float cn = fmaf(fg, cj, ig * gv);
            s_c[b * 13 + j]  = cn;
            s_hn[b * 13 + j] = og * tanh_f(cn);
        }

        // ---- commit h to registers + publish to next layer ----
        #pragma unroll
        for (int j = 0; j < 13; j++) h[j] = s_hn[b * 13 + j];

        float4* dst = (float4*)&g_buf[wp][t][b][0];
        dst[0] = make_float4(h[0], h[1], h[2],  h[3]);
        dst[1] = make_float4(h[4], h[5], h[6],  h[7]);
        dst[2] = make_float4(h[8], h[9], h[10], h[11]);
        g_buf[wp][t][b][12] = h[12];

        __syncthreads();               // all threads' stores precede the flag
        if (b == 0) st_rel(&g_prog[t], l + 1);
    }
}

// Final linear + softmax. One CTA per batch element.
__global__ __launch_bounds__(256) void k_cls(
    const float* __restrict__ w_lin, const float* __restrict__ b_lin,
    float* __restrict__ out)
{
    const int bb  = blockIdx.x;
    const int tid = threadIdx.x;

    float acc[C_];
    #pragma unroll
    for (int c = 0; c < C_; c++) acc[c] = 0.0f;

    for (int t = tid; t < T_; t += 256) {
        const float* xr = &g_buf[1][t][bb][0];   // layer 99 writes parity 1
        float xv[13];
        #pragma unroll
        for (int k = 0; k < 13; k++) xv[k] = xr[k];
        #pragma unroll
        for (int c = 0; c < C_; c++) {
            const float* wr = &w_lin[c * TH_ + t * 13];
            float a = acc[c];
            #pragma unroll
            for (int k = 0; k < 13; k++) a = fmaf(xv[k], wr[k], a);
            acc[c] = a;
        }
    }

    __shared__ float red[256];
    __shared__ float lg[C_];
    #pragma unroll 1
    for (int c = 0; c < C_; c++) {
        red[tid] = acc[c];
        __syncthreads();
        for (int st = 128; st > 0; st >>= 1) {
            if (tid < st) red[tid] += red[tid + st];
            __syncthreads();
        }
        if (tid == 0) lg[c] = red[0] + b_lin[c];
        __syncthreads();
    }

    if (tid == 0) {
        float m = lg[0];
        #pragma unroll
        for (int c = 1; c < C_; c++) m = fmaxf(m, lg[c]);
        float e[C_];
        float ssum = 0.0f;
        #pragma unroll
        for (int c = 0; c < C_; c++) { e[c] = __expf(lg[c] - m); ssum += e[c]; }
        float inv = __fdividef(1.0f, ssum);
        #pragma unroll
        for (int c = 0; c < C_; c++) out[bb * C_ + c] = e[c] * inv;
    }
}

extern "C" void kernel_launch(void* const* d_in, const int* in_sizes, int n_in,
                              void* d_out, int out_size)
{
    const float* input = (const float*)d_in[0];
    const float* w_ih  = (const float*)d_in[1];
    const float* w_hh  = (const float*)d_in[2];
    const float* b_ih  = (const float*)d_in[3];
    const float* b_hh  = (const float*)d_in[4];
    const float* w_lin = (const float*)d_in[5];
    const float* b_lin = (const float*)d_in[6];

    k_reset<<<(T_ + 255) / 256, 256>>>();
    k_lstm<<<L_, 128>>>(input, w_ih, w_hh, b_ih, b_hh);
    k_cls<<<B_, 256>>>(w_lin, b_lin, (float*)d_out);
}

// round 2
// speedup vs baseline: 1.0905x; 1.0905x over previous
#include <cuda_runtime.h>

typedef unsigned long long u64;

#define T_ 1132
#define B_ 128
#define L_ 100
#define TH_ 14716
#define C_ 10

// Double-buffered layer activations + per-(t,warp) progress flags.
__device__ float g_buf[2][T_][B_][16];   // [parity][t][b][padded H]
__device__ int   g_prog[T_][4];          // layers finished (t, warp-slice)

__device__ __forceinline__ int ld_acq(const int* p) {
    int v;
    asm volatile("ld.acquire.gpu.global.b32 %0, [%1];" : "=r"(v) : "l"(p) : "memory");
    return v;
}
__device__ __forceinline__ void st_rel(int* p, int v) {
    asm volatile("st.release.gpu.global.b32 [%0], %1;" :: "l"(p), "r"(v) : "memory");
}

__device__ __forceinline__ u64 pack2(float lo, float hi) {
    u64 d; asm("mov.b64 %0, {%1, %2};" : "=l"(d) : "f"(lo), "f"(hi)); return d;
}
__device__ __forceinline__ void unpack2(u64 v, float& lo, float& hi) {
    asm("mov.b64 {%0, %1}, %2;" : "=f"(lo), "=f"(hi) : "l"(v));
}
// d = a*b + c, two independent fp32 lanes (FFMA2) — PTX-only instruction
__device__ __forceinline__ u64 fma2(u64 a, u64 b, u64 c) {
    u64 d; asm("fma.rn.f32x2 %0, %1, %2, %3;" : "=l"(d) : "l"(a), "l"(b), "l"(c)); return d;
}

__device__ __forceinline__ float sigf(float x) {
    return __fdividef(1.0f, 1.0f + __expf(-x));
}
__device__ __forceinline__ float tanh_f(float x) {
    float a = fabsf(x);
    float e = __expf(-2.0f * a);
    float t = __fdividef(1.0f - e, 1.0f + e);
    return copysignf(t, x);
}

__global__ void k_reset() {
    int i = blockIdx.x * blockDim.x + threadIdx.x;
    if (i < T_ * 4) ((int*)g_prog)[i] = 0;
}

// One CTA per layer, one thread per batch element, one warp per 32-batch slice.
// Wavefront pipeline over t; warps fully independent (per-warp flags).
__global__ __launch_bounds__(128, 1) void k_lstm(
    const float* __restrict__ input,
    const float* __restrict__ w_ih, const float* __restrict__ w_hh,
    const float* __restrict__ b_ih, const float* __restrict__ b_hh)
{
    // Packed weights: s_w[p][j][kk] = {A[2kk], B[2kk], A[2kk+1], B[2kk+1]}
    //   p=0: x-side gates (i,f)   p=1: x-side gates (g,o)
    //   p=2: h-side gates (i,f)   p=3: h-side gates (g,o)
    __shared__ __align__(16) float4 s_w[4][13][7];
    __shared__ __align__(16) float  s_b[13][4];   // {bi, bf, bg, bo} per j

    const int l = blockIdx.x;
    const int b = threadIdx.x;
    const int w = b >> 5;

    // --- load + pack weights ---
    for (int i = b; i < 4 * 13 * 28; i += 128) {
        int p = i / 364, r = i % 364;
        int j = r / 28,  q = r % 28;
        int kk = q >> 2, e = q & 3;
        int k = 2 * kk + (e >> 1);
        int gate = ((p & 1) ? 2 : 0) + (e & 1);
        const float* src = (p < 2) ? w_ih : w_hh;
        float v = (k < 13) ? src[(l * 52 + gate * 13 + j) * 13 + k] : 0.0f;
        ((float*)s_w)[i] = v;
    }
    for (int i = b; i < 52; i += 128) {
        int g = i / 13, j = i % 13;
        s_b[j][g] = b_ih[l * 52 + i] + b_hh[l * 52 + i];
    }
    __syncthreads();

    // --- state in registers (static indices only — loops fully unrolled) ---
    u64 xd[14], hd[14];
    float c[13], hn[13];
    #pragma unroll
    for (int k = 0; k < 14; k++) { xd[k] = 0ull; hd[k] = 0ull; }
    #pragma unroll
    for (int j = 0; j < 13; j++) { c[j] = 0.0f; hn[j] = 0.0f; }

    const int wp = l & 1;
    const int rp = wp ^ 1;
    const u64* pb = (const u64*)s_b;
    int* const myflag_base = &g_prog[0][w];

    for (int t = 0; t < T_; t++) {
        // ---- obtain x(t), replicated into both f32x2 lanes ----
        if (l == 0) {
            const float* ir = &input[(b * T_ + t) * 13];
            #pragma unroll
            for (int k = 0; k < 13; k++) { float v = ir[k]; xd[k] = pack2(v, v); }
        } else {
            const int* fl = &g_prog[t][w];
            while (ld_acq(fl) < l) __nanosleep(20);
            const float4* src = (const float4*)&g_buf[rp][t][b][0];
            float4 v0 = src[0], v1 = src[1], v2 = src[2];
            float  vc = g_buf[rp][t][b][12];
            xd[0]  = pack2(v0.x, v0.x); xd[1]  = pack2(v0.y, v0.y);
            xd[2]  = pack2(v0.z, v0.z); xd[3]  = pack2(v0.w, v0.w);
            xd[4]  = pack2(v1.x, v1.x); xd[5]  = pack2(v1.y, v1.y);
            xd[6]  = pack2(v1.z, v1.z); xd[7]  = pack2(v1.w, v1.w);
            xd[8]  = pack2(v2.x, v2.x); xd[9]  = pack2(v2.y, v2.y);
            xd[10] = pack2(v2.z, v2.z); xd[11] = pack2(v2.w, v2.w);
            xd[12] = pack2(vc, vc);
        }

        // ---- gates + state update, fully unrolled over hidden unit j ----
        #pragma unroll
        for (int j = 0; j < 13; j++) {
            u64 aif = pb[j * 2];
            u64 ago = pb[j * 2 + 1];
            #pragma unroll
            for (int kk = 0; kk < 7; kk++) {
                ulonglong2 wxif = *(const ulonglong2*)&s_w[0][j][kk];
                ulonglong2 wxgo = *(const ulonglong2*)&s_w[1][j][kk];
                ulonglong2 whif = *(const ulonglong2*)&s_w[2][j][kk];
                ulonglong2 whgo = *(const ulonglong2*)&s_w[3][j][kk];
                aif = fma2(wxif.x, xd[2 * kk],     aif);
                aif = fma2(wxif.y, xd[2 * kk + 1], aif);
                ago = fma2(wxgo.x, xd[2 * kk],     ago);
                ago = fma2(wxgo.y, xd[2 * kk + 1], ago);
                aif = fma2(whif.x, hd[2 * kk],     aif);
                aif = fma2(whif.y, hd[2 * kk + 1], aif);
                ago = fma2(whgo.x, hd[2 * kk],     ago);
                ago = fma2(whgo.y, hd[2 * kk + 1], ago);
            }
            float ai, af, ag, ao;
            unpack2(aif, ai, af);
            unpack2(ago, ag, ao);
            float ig = sigf(ai), fg = sigf(af), gv = tanh_f(ag), og = sigf(ao);
            float cn = fmaf(fg, c[j], ig * gv);
            c[j]  = cn;
            hn[j] = og * tanh_f(cn);
        }

        // ---- commit h (next-t operand) ----
        #pragma unroll
        for (int j = 0; j < 13; j++) hd[j] = pack2(hn[j], hn[j]);

        // ---- publish to next layer ----
        float4* dst = (float4*)&g_buf[wp][t][b][0];
        dst[0] = make_float4(hn[0], hn[1], hn[2],  hn[3]);
        dst[1] = make_float4(hn[4], hn[5], hn[6],  hn[7]);
        dst[2] = make_float4(hn[8], hn[9], hn[10], hn[11]);
        g_buf[wp][t][b][12] = hn[12];

        __syncwarp();
        if ((b & 31) == 0) st_rel(myflag_base + t * 4, l + 1);
    }
}

// Final linear + softmax. One CTA per batch element.
__global__ __launch_bounds__(256) void k_cls(
    const float* __restrict__ w_lin, const float* __restrict__ b_lin,
    float* __restrict__ out)
{
    const int bb  = blockIdx.x;
    const int tid = threadIdx.x;

    float acc[C_];
    #pragma unroll
    for (int cc = 0; cc < C_; cc++) acc[cc] = 0.0f;

    for (int t = tid; t < T_; t += 256) {
        const float* xr = &g_buf[1][t][bb][0];   // layer 99 writes parity 1
        float xv[13];
        #pragma unroll
        for (int k = 0; k < 13; k++) xv[k] = xr[k];
        #pragma unroll
        for (int cc = 0; cc < C_; cc++) {
            const float* wr = &w_lin[cc * TH_ + t * 13];
            float a = acc[cc];
            #pragma unroll
            for (int k = 0; k < 13; k++) a = fmaf(xv[k], wr[k], a);
            acc[cc] = a;
        }
    }

    __shared__ float red[256];
    __shared__ float lg[C_];
    #pragma unroll 1
    for (int cc = 0; cc < C_; cc++) {
        red[tid] = acc[cc];
        __syncthreads();
        for (int st = 128; st > 0; st >>= 1) {
            if (tid < st) red[tid] += red[tid + st];
            __syncthreads();
        }
        if (tid == 0) lg[cc] = red[0] + b_lin[cc];
        __syncthreads();
    }

    if (tid == 0) {
        float m = lg[0];
        #pragma unroll
        for (int cc = 1; cc < C_; cc++) m = fmaxf(m, lg[cc]);
        float e[C_];
        float ssum = 0.0f;
        #pragma unroll
        for (int cc = 0; cc < C_; cc++) { e[cc] = __expf(lg[cc] - m); ssum += e[cc]; }
        float inv = __fdividef(1.0f, ssum);
        #pragma unroll
        for (int cc = 0; cc < C_; cc++) out[bb * C_ + cc] = e[cc] * inv;
    }
}

extern "C" void kernel_launch(void* const* d_in, const int* in_sizes, int n_in,
                              void* d_out, int out_size)
{
    const float* input = (const float*)d_in[0];
    const float* w_ih  = (const float*)d_in[1];
    const float* w_hh  = (const float*)d_in[2];
    const float* b_ih  = (const float*)d_in[3];
    const float* b_hh  = (const float*)d_in[4];
    const float* w_lin = (const float*)d_in[5];
    const float* b_lin = (const float*)d_in[6];

    k_reset<<<(T_ * 4 + 255) / 256, 256>>>();
    k_lstm<<<L_, 128>>>(input, w_ih, w_hh, b_ih, b_hh);
    k_cls<<<B_, 256>>>(w_lin, b_lin, (float*)d_out);
}